// round 16
// baseline (speedup 1.0000x reference)
#include <cuda_runtime.h>
#include <cstdint>

#define N_NODES 1024
#define D 64
#define ALPHA_F 0.2f
#define MASK_VAL_F -1000000000.0f
#define LN_EPS_F 1e-5f

// ---------------- scratch (no allocations allowed) ----------------
__device__ float g_Wh[N_NODES * D];
__device__ float g_ei[N_NODES * D];   // h @ E_i + edge_b (folded)
__device__ float g_ej[N_NODES * D];   // h @ E_j
__device__ float g_qi[N_NODES * D];   // Wh @ A_i + attn_b1 (folded)
__device__ float g_kj[N_NODES * D];   // Wh @ A_j
__device__ float g_e[N_NODES * N_NODES];

// ---------------- helpers ----------------
__device__ __forceinline__ float warpReduceSum(float v) {
    #pragma unroll
    for (int o = 16; o > 0; o >>= 1) v += __shfl_xor_sync(0xffffffffu, v, o);
    return v;
}
// pack {lo, hi} floats -> bf16x2 (element0 = lo)
__device__ __forceinline__ uint32_t pack_bf16x2(float lo, float hi) {
    uint32_t r;
    asm("cvt.rn.bf16x2.f32 %0, %1, %2;" : "=r"(r) : "f"(hi), "f"(lo));
    return r;
}
// leaky(a+b) entirely in bf16x2: t=a*1+b (one rounding), m=t*alpha, max(t,m).
// 3 instructions per 2 elements.
#define BF2_ONE   0x3F803F80u
#define BF2_ALPHA 0x3E4D3E4Du   // bf16(0.2) x2
#define BF2_ZERO  0x00000000u
__device__ __forceinline__ uint32_t leakyadd2(uint32_t a, uint32_t b) {
    uint32_t t, m, r;
    asm("fma.rn.bf16x2 %0, %1, %2, %3;" : "=r"(t) : "r"(a), "r"(BF2_ONE),   "r"(b));
    asm("fma.rn.bf16x2 %0, %1, %2, %3;" : "=r"(m) : "r"(t), "r"(BF2_ALPHA), "r"(BF2_ZERO));
    asm("max.bf16x2 %0, %1, %2;"        : "=r"(r) : "r"(t), "r"(m));
    return r;
}
__device__ __forceinline__ void mma_bf16_16x8x16(
    float& c0, float& c1, float& c2, float& c3,
    uint32_t a0, uint32_t a1, uint32_t a2, uint32_t a3,
    uint32_t b0, uint32_t b1)
{
    asm volatile(
        "mma.sync.aligned.m16n8k16.row.col.f32.bf16.bf16.f32 "
        "{%0,%1,%2,%3}, {%4,%5,%6,%7}, {%8,%9}, {%0,%1,%2,%3};"
        : "+f"(c0), "+f"(c1), "+f"(c2), "+f"(c3)
        : "r"(a0), "r"(a1), "r"(a2), "r"(a3), "r"(b0), "r"(b1));
}
__device__ __forceinline__ float leaky(float s) { return fmaxf(s, ALPHA_F * s); }

// ================================================================
// Kernel 1: per-node projections. ALL weights staged upfront (80KB).
// 128 blocks x 8 nodes, 2 nodes/thread.
// ================================================================
__global__ void __launch_bounds__(256) prep_kernel(
    const float* __restrict__ h, const float* __restrict__ W,
    const float* __restrict__ attn_w1, const float* __restrict__ attn_b1,
    const float* __restrict__ edge_w, const float* __restrict__ edge_b)
{
    __shared__ float sWt[20480];          // 80KB: W | E_i | E_j | A_i | A_j
    __shared__ float sh[8][64];
    __shared__ float swh[8][64];
    const int t = threadIdx.x;
    const int d = t & 63;
    const int n0 = (t >> 6) * 2;
    const int nb = blockIdx.x * 8;

    #pragma unroll
    for (int x = t; x < 1024; x += 256)
        ((float4*)sWt)[x] = ((const float4*)W)[x];
    #pragma unroll
    for (int x = t; x < 2048; x += 256)
        ((float4*)(sWt + 4096))[x] = ((const float4*)edge_w)[x];
    #pragma unroll
    for (int x = t; x < 2048; x += 256)
        ((float4*)(sWt + 12288))[x] = ((const float4*)attn_w1)[x];
    if (t < 128)
        ((float4*)sh)[t] = ((const float4*)(h + nb * D))[t];
    __syncthreads();

    float wh0 = 0.f, wh1 = 0.f;
    float ei0 = edge_b[d], ei1 = ei0;
    float ej0 = 0.f, ej1 = 0.f;
    #pragma unroll 8
    for (int k = 0; k < D; ++k) {
        const float w  = sWt[k * 64 + d];
        const float e1 = sWt[4096 + k * 64 + d];
        const float e2 = sWt[8192 + k * 64 + d];
        const float h0 = sh[n0][k], h1 = sh[n0 + 1][k];
        wh0 += h0 * w;  wh1 += h1 * w;
        ei0 += h0 * e1; ei1 += h1 * e1;
        ej0 += h0 * e2; ej1 += h1 * e2;
    }
    const int na = nb + n0;
    g_Wh[na * D + d] = wh0;       g_Wh[(na + 1) * D + d] = wh1;
    g_ei[na * D + d] = ei0;       g_ei[(na + 1) * D + d] = ei1;
    g_ej[na * D + d] = ej0;       g_ej[(na + 1) * D + d] = ej1;
    swh[n0][d] = wh0;             swh[n0 + 1][d] = wh1;
    __syncthreads();

    float qi0 = attn_b1[d], qi1 = qi0;
    float kj0 = 0.f, kj1 = 0.f;
    #pragma unroll 8
    for (int k = 0; k < D; ++k) {
        const float a1 = sWt[12288 + k * 64 + d];
        const float a2 = sWt[16384 + k * 64 + d];
        const float w0 = swh[n0][k], w1 = swh[n0 + 1][k];
        qi0 += w0 * a1; qi1 += w1 * a1;
        kj0 += w0 * a2; kj1 += w1 * a2;
    }
    g_qi[na * D + d] = qi0;       g_qi[(na + 1) * D + d] = qi1;
    g_kj[na * D + d] = kj0;       g_kj[(na + 1) * D + d] = kj1;
}

// ================================================================
// Kernel 2: attention scores via mma.sync bf16 (m16n8k16).
//   8 warps x 16 j, full d=64 per warp. Register-resident i-invariants.
//   Dual-i interleave; epilogue dot-with-w2 via MMA; adj prefetch.
//   NEW: ei/ej staged as bf16x2 -> 3-instruction af-build (leakyadd2).
// ================================================================
#define CHUNK_I 58
#define N_ICHUNKS 18

__global__ void __launch_bounds__(256, 1) escore_hmma_kernel(
    const float* __restrict__ attn_w1, const float* __restrict__ attn_w2,
    const float* __restrict__ attn_b2, const int* __restrict__ adj)
{
    __shared__ uint32_t sEjH[128][36];      // bf16x2, pad 36
    __shared__ float    sKj[128][68];
    __shared__ float    sAe[64][68];
    __shared__ uint32_t sEiH[CHUNK_I][36];  // bf16x2
    __shared__ float    sQi[CHUNK_I][64];
    __shared__ float    sW2[64];

    const int tid  = threadIdx.x;
    const int wid  = tid >> 5;
    const int lane = tid & 31;
    const int gid  = lane >> 2;     // 0..7
    const int tig  = lane & 3;      // 0..3
    const int j0   = blockIdx.x * 128;
    const int iBase = blockIdx.y * CHUNK_I;
    const int n_i  = min(CHUNK_I, N_NODES - iBase);   // 58 or 38 (both even)

    // ---- stage block tiles ----
    for (int x = tid; x < 128 * 32; x += 256) {
        const int j = x >> 5, kp = x & 31;
        const float2 v = ((const float2*)(g_ej + (j0 + j) * D))[kp];
        sEjH[j][kp] = pack_bf16x2(v.x, v.y);
    }
    for (int x = tid; x < 128 * 64; x += 256) {
        const int j = x >> 6, k = x & 63;
        sKj[j][k] = g_kj[(j0 + j) * D + k];
    }
    for (int x = tid; x < 64 * 64; x += 256) {
        const int k = x >> 6, d = x & 63;
        sAe[k][d] = attn_w1[(128 + k) * D + d];   // A_e
    }
    for (int x = tid; x < n_i * 32; x += 256) {
        const int ii = x >> 5, kp = x & 31;
        const float2 v = ((const float2*)(g_ei + (iBase + ii) * D))[kp];
        sEiH[ii][kp] = pack_bf16x2(v.x, v.y);
    }
    for (int x = tid; x < n_i * 64; x += 256) {
        const int ii = x >> 6, d = x & 63;
        sQi[ii][d] = g_qi[(iBase + ii) * D + d];
    }
    if (tid < 64) sW2[tid] = attn_w2[tid];
    __syncthreads();

    // ---- B fragments (bf16, register-resident, whole kernel): 64 regs ----
    uint32_t Bf[4][8][2];
    #pragma unroll
    for (int s = 0; s < 4; ++s)
        #pragma unroll
        for (int nt = 0; nt < 8; ++nt) {
            const int dd = 8 * nt + gid;
            const int kb = 16 * s + 2 * tig;
            Bf[s][nt][0] = pack_bf16x2(sAe[kb][dd],     sAe[kb + 1][dd]);
            Bf[s][nt][1] = pack_bf16x2(sAe[kb + 8][dd], sAe[kb + 9][dd]);
        }

    const int jw = wid * 16;
    const float b2 = attn_b2[0];

    // ---- hoist ej bf16x2 fragments (i-invariant): 16 regs ----
    uint32_t ejaH0[4], ejbH0[4], ejaH1[4], ejbH1[4];
    #pragma unroll
    for (int s = 0; s < 4; ++s) {
        const int kp = 8 * s + tig;
        ejaH0[s] = sEjH[jw + gid][kp];
        ejbH0[s] = sEjH[jw + gid][kp + 4];
        ejaH1[s] = sEjH[jw + gid + 8][kp];
        ejbH1[s] = sEjH[jw + gid + 8][kp + 4];
    }

    // ---- hoist kj fragments (i-invariant, C-layout): 32 regs ----
    float2 kj0r[8], kj1r[8];
    #pragma unroll
    for (int nt = 0; nt < 8; ++nt) {
        const int off = 8 * nt + 2 * tig;
        kj0r[nt] = *(const float2*)&sKj[jw + gid][off];
        kj1r[nt] = *(const float2*)&sKj[jw + gid + 8][off];
    }

    // ---- hoist w2 B-fragments for the epilogue MMA: 8 regs ----
    uint32_t w2B[4][2];
    #pragma unroll
    for (int s = 0; s < 4; ++s) {
        const int kb = 16 * s + 2 * tig;
        w2B[s][0] = pack_bf16x2(sW2[kb],     sW2[kb + 1]);
        w2B[s][1] = pack_bf16x2(sW2[kb + 8], sW2[kb + 9]);
    }

    const int jA = j0 + jw + gid;
    const int jB = jA + 8;
    const int n_pairs = n_i >> 1;

    // ---- dual-i main loop: 2 independent streams per warp ----
    #pragma unroll 1
    for (int m = 0; m < n_pairs; ++m) {
        const int ii0 = 2 * m, ii1 = 2 * m + 1;
        const int i0 = iBase + ii0, i1 = iBase + ii1;

        // prefetch adj masks NOW; consumed ~400 instructions later
        const int adj0A = adj[i0 * N_NODES + jA];
        const int adj0B = adj[i0 * N_NODES + jB];
        const int adj1A = adj[i1 * N_NODES + jA];
        const int adj1B = adj[i1 * N_NODES + jB];

        // build A fragments for both i's (pure bf16x2 SIMD: 3 instr/pack)
        uint32_t af0[4][4], af1[4][4];
        #pragma unroll
        for (int s = 0; s < 4; ++s) {
            const int kp = 8 * s + tig;
            const uint32_t e0a = sEiH[ii0][kp];
            const uint32_t e0b = sEiH[ii0][kp + 4];
            const uint32_t e1a = sEiH[ii1][kp];
            const uint32_t e1b = sEiH[ii1][kp + 4];
            af0[s][0] = leakyadd2(e0a, ejaH0[s]);
            af0[s][1] = leakyadd2(e0a, ejaH1[s]);
            af0[s][2] = leakyadd2(e0b, ejbH0[s]);
            af0[s][3] = leakyadd2(e0b, ejbH1[s]);
            af1[s][0] = leakyadd2(e1a, ejaH0[s]);
            af1[s][1] = leakyadd2(e1a, ejaH1[s]);
            af1[s][2] = leakyadd2(e1b, ejbH0[s]);
            af1[s][3] = leakyadd2(e1b, ejbH1[s]);
        }

        // acc init = qi + kj(regs) for both i's
        float acc0[8][4], acc1[8][4];
        #pragma unroll
        for (int nt = 0; nt < 8; ++nt) {
            const int off = 8 * nt + 2 * tig;
            const float2 q0 = *(const float2*)&sQi[ii0][off];
            const float2 q1 = *(const float2*)&sQi[ii1][off];
            acc0[nt][0] = q0.x + kj0r[nt].x; acc0[nt][1] = q0.y + kj0r[nt].y;
            acc0[nt][2] = q0.x + kj1r[nt].x; acc0[nt][3] = q0.y + kj1r[nt].y;
            acc1[nt][0] = q1.x + kj0r[nt].x; acc1[nt][1] = q1.y + kj0r[nt].y;
            acc1[nt][2] = q1.x + kj1r[nt].x; acc1[nt][3] = q1.y + kj1r[nt].y;
        }

        // interleaved MMA sets: 16 independent chains
        #pragma unroll
        for (int s = 0; s < 4; ++s) {
            #pragma unroll
            for (int nt = 0; nt < 8; ++nt) {
                mma_bf16_16x8x16(acc0[nt][0], acc0[nt][1], acc0[nt][2], acc0[nt][3],
                                 af0[s][0], af0[s][1], af0[s][2], af0[s][3],
                                 Bf[s][nt][0], Bf[s][nt][1]);
                mma_bf16_16x8x16(acc1[nt][0], acc1[nt][1], acc1[nt][2], acc1[nt][3],
                                 af1[s][0], af1[s][1], af1[s][2], af1[s][3],
                                 Bf[s][nt][0], Bf[s][nt][1]);
            }
        }

        // ---- epilogue via MMA: e[j] = sum_d leaky(pre[j,d]) * w2[d] ----
        float c0[4] = {0.f, 0.f, 0.f, 0.f};
        float c1[4] = {0.f, 0.f, 0.f, 0.f};
        #pragma unroll
        for (int sp = 0; sp < 4; ++sp) {
            const uint32_t a00 = pack_bf16x2(leaky(acc0[2*sp][0]),   leaky(acc0[2*sp][1]));
            const uint32_t a01 = pack_bf16x2(leaky(acc0[2*sp][2]),   leaky(acc0[2*sp][3]));
            const uint32_t a02 = pack_bf16x2(leaky(acc0[2*sp+1][0]), leaky(acc0[2*sp+1][1]));
            const uint32_t a03 = pack_bf16x2(leaky(acc0[2*sp+1][2]), leaky(acc0[2*sp+1][3]));
            const uint32_t a10 = pack_bf16x2(leaky(acc1[2*sp][0]),   leaky(acc1[2*sp][1]));
            const uint32_t a11 = pack_bf16x2(leaky(acc1[2*sp][2]),   leaky(acc1[2*sp][3]));
            const uint32_t a12 = pack_bf16x2(leaky(acc1[2*sp+1][0]), leaky(acc1[2*sp+1][1]));
            const uint32_t a13 = pack_bf16x2(leaky(acc1[2*sp+1][2]), leaky(acc1[2*sp+1][3]));
            mma_bf16_16x8x16(c0[0], c0[1], c0[2], c0[3],
                             a00, a01, a02, a03, w2B[sp][0], w2B[sp][1]);
            mma_bf16_16x8x16(c1[0], c1[1], c1[2], c1[3],
                             a10, a11, a12, a13, w2B[sp][0], w2B[sp][1]);
        }

        if (tig == 0) {
            float a0 = c0[0] + b2, a1 = c0[2] + b2;
            float d0 = c1[0] + b2, d1 = c1[2] + b2;
            if (adj0A == 0) a0 = MASK_VAL_F;
            if (adj0B == 0) a1 = MASK_VAL_F;
            if (adj1A == 0) d0 = MASK_VAL_F;
            if (adj1B == 0) d1 = MASK_VAL_F;
            g_e[i0 * N_NODES + jA] = a0;
            g_e[i0 * N_NODES + jB] = a1;
            g_e[i1 * N_NODES + jA] = d0;
            g_e[i1 * N_NODES + jB] = d1;
        }
    }
}

// ================================================================
// Kernel 3: softmax + aggregate + LN; 8 rows per block (Wh reuse, 1 wave).
// No max pass — e analytically bounded; masked -1e9 underflows via -87 clamp.
// ================================================================
#define R8 8
__global__ void __launch_bounds__(256) softmax_ln_kernel(
    const float* __restrict__ h, const float* __restrict__ ln_g,
    const float* __restrict__ ln_b, float* __restrict__ out)
{
    __shared__ float sp[R8][N_NODES];       // 32KB
    __shared__ float red[R8][8];
    __shared__ float part[R8][4][64];       // 8KB
    __shared__ float shp[R8][64];
    __shared__ float sInv[R8], sMu[R8], sVar[R8];

    const int i0 = blockIdx.x * R8;
    const int t = threadIdx.x;
    const int lane = t & 31, wid = t >> 5;

    float s[R8];
    #pragma unroll
    for (int r = 0; r < R8; ++r) s[r] = 0.f;
    for (int j = t; j < N_NODES; j += 256) {
        #pragma unroll
        for (int r = 0; r < R8; ++r) {
            const float v = g_e[(i0 + r) * N_NODES + j];
            const float p = __expf(fmaxf(v, -87.0f));
            sp[r][j] = p;
            s[r] += p;
        }
    }
    #pragma unroll
    for (int r = 0; r < R8; ++r) {
        s[r] = warpReduceSum(s[r]);
        if (lane == 0) red[r][wid] = s[r];
    }
    __syncthreads();
    if (t < R8) {
        float ss = 0.f;
        #pragma unroll
        for (int w = 0; w < 8; ++w) ss += red[t][w];
        sInv[t] = 1.0f / ss;
    }
    __syncthreads();

    const int g = t >> 6, d = t & 63;
    const int jb = g * 256;
    float a[R8];
    #pragma unroll
    for (int r = 0; r < R8; ++r) a[r] = 0.f;
    #pragma unroll 2
    for (int jj = 0; jj < 256; jj += 4) {
        const float w0 = g_Wh[(jb + jj + 0) * D + d];
        const float w1 = g_Wh[(jb + jj + 1) * D + d];
        const float w2 = g_Wh[(jb + jj + 2) * D + d];
        const float w3 = g_Wh[(jb + jj + 3) * D + d];
        #pragma unroll
        for (int r = 0; r < R8; ++r) {
            const float4 p = *(const float4*)&sp[r][jb + jj];
            a[r] += p.x * w0 + p.y * w1 + p.z * w2 + p.w * w3;
        }
    }
    #pragma unroll
    for (int r = 0; r < R8; ++r) part[r][g][d] = a[r];
    __syncthreads();

    #pragma unroll
    for (int it = 0; it < 2; ++it) {
        const int idx = t + it * 256;
        const int r = idx >> 6, dd = idx & 63;
        const float hp = (part[r][0][dd] + part[r][1][dd] + part[r][2][dd] + part[r][3][dd])
                         * sInv[r] + h[(i0 + r) * D + dd];
        shp[r][dd] = hp;
    }
    __syncthreads();

    {
        const int r = wid;
        float v = shp[r][lane] + shp[r][lane + 32];
        v = warpReduceSum(v);
        if (lane == 0) sMu[r] = v * (1.0f / 64.0f);
    }
    __syncthreads();
    {
        const int r = wid;
        const float mu = sMu[r];
        const float d0 = shp[r][lane] - mu, d1 = shp[r][lane + 32] - mu;
        float v = d0 * d0 + d1 * d1;
        v = warpReduceSum(v);
        if (lane == 0) sVar[r] = v * (1.0f / 64.0f);
    }
    __syncthreads();

    #pragma unroll
    for (int it = 0; it < 2; ++it) {
        const int idx = t + it * 256;
        const int r = idx >> 6, dd = idx & 63;
        const float mu = sMu[r];
        const float rstd = rsqrtf(sVar[r] + LN_EPS_F);
        out[(i0 + r) * D + dd] = (shp[r][dd] - mu) * rstd * ln_g[dd] + ln_b[dd];
    }
}

// ================================================================
extern "C" void kernel_launch(void* const* d_in, const int* in_sizes, int n_in,
                              void* d_out, int out_size) {
    const float* h        = (const float*)d_in[0];
    const int*   adj      = (const int*)  d_in[1];
    const float* W        = (const float*)d_in[2];
    const float* attn_w1  = (const float*)d_in[3];
    const float* attn_b1  = (const float*)d_in[4];
    const float* attn_w2  = (const float*)d_in[5];
    const float* attn_b2  = (const float*)d_in[6];
    const float* edge_w   = (const float*)d_in[7];
    const float* edge_b   = (const float*)d_in[8];
    const float* ln_g     = (const float*)d_in[9];
    const float* ln_b     = (const float*)d_in[10];
    float* out = (float*)d_out;

    prep_kernel<<<N_NODES / 8, 256>>>(h, W, attn_w1, attn_b1, edge_w, edge_b);

    dim3 grid(N_NODES / 128, N_ICHUNKS);
    escore_hmma_kernel<<<grid, 256>>>(attn_w1, attn_w2, attn_b2, adj);

    softmax_ln_kernel<<<N_NODES / R8, 256>>>(h, ln_g, ln_b, out);
}

// round 17
// speedup vs baseline: 1.0022x; 1.0022x over previous
#include <cuda_runtime.h>
#include <cstdint>

#define N_NODES 1024
#define D 64
#define ALPHA_F 0.2f
#define MASK_VAL_F -1000000000.0f
#define LN_EPS_F 1e-5f

// ---------------- scratch (no allocations allowed) ----------------
__device__ float g_Wh[N_NODES * D];
__device__ float g_ei[N_NODES * D];   // h @ E_i + edge_b (folded)
__device__ float g_ej[N_NODES * D];   // h @ E_j
__device__ float g_qi[N_NODES * D];   // Wh @ A_i + attn_b1 (folded)
__device__ float g_kj[N_NODES * D];   // Wh @ A_j
__device__ float g_e[N_NODES * N_NODES];

// ---------------- helpers ----------------
__device__ __forceinline__ float warpReduceSum(float v) {
    #pragma unroll
    for (int o = 16; o > 0; o >>= 1) v += __shfl_xor_sync(0xffffffffu, v, o);
    return v;
}
// pack {lo, hi} floats -> bf16x2 (element0 = lo)
__device__ __forceinline__ uint32_t pack_bf16x2(float lo, float hi) {
    uint32_t r;
    asm("cvt.rn.bf16x2.f32 %0, %1, %2;" : "=r"(r) : "f"(hi), "f"(lo));
    return r;
}
// leaky(a+b) entirely in bf16x2: t=a*1+b (one rounding), m=t*alpha, max(t,m).
#define BF2_ONE   0x3F803F80u
#define BF2_ALPHA 0x3E4D3E4Du   // bf16(0.2) x2
#define BF2_ZERO  0x00000000u
__device__ __forceinline__ uint32_t leakyadd2(uint32_t a, uint32_t b) {
    uint32_t t, m, r;
    asm("fma.rn.bf16x2 %0, %1, %2, %3;" : "=r"(t) : "r"(a), "r"(BF2_ONE),   "r"(b));
    asm("fma.rn.bf16x2 %0, %1, %2, %3;" : "=r"(m) : "r"(t), "r"(BF2_ALPHA), "r"(BF2_ZERO));
    asm("max.bf16x2 %0, %1, %2;"        : "=r"(r) : "r"(t), "r"(m));
    return r;
}
__device__ __forceinline__ void mma_bf16_16x8x16(
    float& c0, float& c1, float& c2, float& c3,
    uint32_t a0, uint32_t a1, uint32_t a2, uint32_t a3,
    uint32_t b0, uint32_t b1)
{
    asm volatile(
        "mma.sync.aligned.m16n8k16.row.col.f32.bf16.bf16.f32 "
        "{%0,%1,%2,%3}, {%4,%5,%6,%7}, {%8,%9}, {%0,%1,%2,%3};"
        : "+f"(c0), "+f"(c1), "+f"(c2), "+f"(c3)
        : "r"(a0), "r"(a1), "r"(a2), "r"(a3), "r"(b0), "r"(b1));
}
__device__ __forceinline__ float leaky(float s) { return fmaxf(s, ALPHA_F * s); }

// ================================================================
// Kernel 1: per-node projections. ALL weights staged upfront (80KB).
// 128 blocks x 8 nodes, 2 nodes/thread.
// ================================================================
__global__ void __launch_bounds__(256) prep_kernel(
    const float* __restrict__ h, const float* __restrict__ W,
    const float* __restrict__ attn_w1, const float* __restrict__ attn_b1,
    const float* __restrict__ edge_w, const float* __restrict__ edge_b)
{
    __shared__ float sWt[20480];          // 80KB: W | E_i | E_j | A_i | A_j
    __shared__ float sh[8][64];
    __shared__ float swh[8][64];
    const int t = threadIdx.x;
    const int d = t & 63;
    const int n0 = (t >> 6) * 2;
    const int nb = blockIdx.x * 8;

    #pragma unroll
    for (int x = t; x < 1024; x += 256)
        ((float4*)sWt)[x] = ((const float4*)W)[x];
    #pragma unroll
    for (int x = t; x < 2048; x += 256)
        ((float4*)(sWt + 4096))[x] = ((const float4*)edge_w)[x];
    #pragma unroll
    for (int x = t; x < 2048; x += 256)
        ((float4*)(sWt + 12288))[x] = ((const float4*)attn_w1)[x];
    if (t < 128)
        ((float4*)sh)[t] = ((const float4*)(h + nb * D))[t];
    __syncthreads();

    float wh0 = 0.f, wh1 = 0.f;
    float ei0 = edge_b[d], ei1 = ei0;
    float ej0 = 0.f, ej1 = 0.f;
    #pragma unroll 8
    for (int k = 0; k < D; ++k) {
        const float w  = sWt[k * 64 + d];
        const float e1 = sWt[4096 + k * 64 + d];
        const float e2 = sWt[8192 + k * 64 + d];
        const float h0 = sh[n0][k], h1 = sh[n0 + 1][k];
        wh0 += h0 * w;  wh1 += h1 * w;
        ei0 += h0 * e1; ei1 += h1 * e1;
        ej0 += h0 * e2; ej1 += h1 * e2;
    }
    const int na = nb + n0;
    g_Wh[na * D + d] = wh0;       g_Wh[(na + 1) * D + d] = wh1;
    g_ei[na * D + d] = ei0;       g_ei[(na + 1) * D + d] = ei1;
    g_ej[na * D + d] = ej0;       g_ej[(na + 1) * D + d] = ej1;
    swh[n0][d] = wh0;             swh[n0 + 1][d] = wh1;
    __syncthreads();

    float qi0 = attn_b1[d], qi1 = qi0;
    float kj0 = 0.f, kj1 = 0.f;
    #pragma unroll 8
    for (int k = 0; k < D; ++k) {
        const float a1 = sWt[12288 + k * 64 + d];
        const float a2 = sWt[16384 + k * 64 + d];
        const float w0 = swh[n0][k], w1 = swh[n0 + 1][k];
        qi0 += w0 * a1; qi1 += w1 * a1;
        kj0 += w0 * a2; kj1 += w1 * a2;
    }
    g_qi[na * D + d] = qi0;       g_qi[(na + 1) * D + d] = qi1;
    g_kj[na * D + d] = kj0;       g_kj[(na + 1) * D + d] = kj1;
}

// ================================================================
// Kernel 2: attention scores via mma.sync bf16 (m16n8k16).
//   8 warps x 16 j, full d=64 per warp. Register-resident i-invariants.
//   Dual-i interleave; bf16x2 af-build; adj prefetch; 144-block grid.
//   NEW: epilogue back to SCALAR (fma pipe) — tensor pipe is the
//   bottleneck; remove its 20% epilogue-MMA load.
// ================================================================
#define CHUNK_I 58
#define N_ICHUNKS 18

__global__ void __launch_bounds__(256, 1) escore_hmma_kernel(
    const float* __restrict__ attn_w1, const float* __restrict__ attn_w2,
    const float* __restrict__ attn_b2, const int* __restrict__ adj)
{
    __shared__ uint32_t sEjH[128][36];      // bf16x2, pad 36
    __shared__ float    sKj[128][68];
    __shared__ float    sAe[64][68];
    __shared__ uint32_t sEiH[CHUNK_I][36];  // bf16x2
    __shared__ float    sQi[CHUNK_I][64];
    __shared__ float    sW2[64];

    const int tid  = threadIdx.x;
    const int wid  = tid >> 5;
    const int lane = tid & 31;
    const int gid  = lane >> 2;     // 0..7
    const int tig  = lane & 3;      // 0..3
    const int j0   = blockIdx.x * 128;
    const int iBase = blockIdx.y * CHUNK_I;
    const int n_i  = min(CHUNK_I, N_NODES - iBase);   // 58 or 38 (both even)

    // ---- stage block tiles ----
    for (int x = tid; x < 128 * 32; x += 256) {
        const int j = x >> 5, kp = x & 31;
        const float2 v = ((const float2*)(g_ej + (j0 + j) * D))[kp];
        sEjH[j][kp] = pack_bf16x2(v.x, v.y);
    }
    for (int x = tid; x < 128 * 64; x += 256) {
        const int j = x >> 6, k = x & 63;
        sKj[j][k] = g_kj[(j0 + j) * D + k];
    }
    for (int x = tid; x < 64 * 64; x += 256) {
        const int k = x >> 6, d = x & 63;
        sAe[k][d] = attn_w1[(128 + k) * D + d];   // A_e
    }
    for (int x = tid; x < n_i * 32; x += 256) {
        const int ii = x >> 5, kp = x & 31;
        const float2 v = ((const float2*)(g_ei + (iBase + ii) * D))[kp];
        sEiH[ii][kp] = pack_bf16x2(v.x, v.y);
    }
    for (int x = tid; x < n_i * 64; x += 256) {
        const int ii = x >> 6, d = x & 63;
        sQi[ii][d] = g_qi[(iBase + ii) * D + d];
    }
    if (tid < 64) sW2[tid] = attn_w2[tid];
    __syncthreads();

    // ---- B fragments (bf16, register-resident, whole kernel): 64 regs ----
    uint32_t Bf[4][8][2];
    #pragma unroll
    for (int s = 0; s < 4; ++s)
        #pragma unroll
        for (int nt = 0; nt < 8; ++nt) {
            const int dd = 8 * nt + gid;
            const int kb = 16 * s + 2 * tig;
            Bf[s][nt][0] = pack_bf16x2(sAe[kb][dd],     sAe[kb + 1][dd]);
            Bf[s][nt][1] = pack_bf16x2(sAe[kb + 8][dd], sAe[kb + 9][dd]);
        }

    const int jw = wid * 16;
    const float b2 = attn_b2[0];

    // ---- hoist ej bf16x2 fragments (i-invariant): 16 regs ----
    uint32_t ejaH0[4], ejbH0[4], ejaH1[4], ejbH1[4];
    #pragma unroll
    for (int s = 0; s < 4; ++s) {
        const int kp = 8 * s + tig;
        ejaH0[s] = sEjH[jw + gid][kp];
        ejbH0[s] = sEjH[jw + gid][kp + 4];
        ejaH1[s] = sEjH[jw + gid + 8][kp];
        ejbH1[s] = sEjH[jw + gid + 8][kp + 4];
    }

    // ---- hoist kj fragments (i-invariant, C-layout): 32 regs ----
    float2 kj0r[8], kj1r[8];
    #pragma unroll
    for (int nt = 0; nt < 8; ++nt) {
        const int off = 8 * nt + 2 * tig;
        kj0r[nt] = *(const float2*)&sKj[jw + gid][off];
        kj1r[nt] = *(const float2*)&sKj[jw + gid + 8][off];
    }

    const int jA = j0 + jw + gid;
    const int jB = jA + 8;
    const int n_pairs = n_i >> 1;

    // ---- dual-i main loop: 2 independent streams per warp ----
    #pragma unroll 1
    for (int m = 0; m < n_pairs; ++m) {
        const int ii0 = 2 * m, ii1 = 2 * m + 1;
        const int i0 = iBase + ii0, i1 = iBase + ii1;

        // prefetch adj masks NOW; consumed ~500 instructions later
        const int adj0A = adj[i0 * N_NODES + jA];
        const int adj0B = adj[i0 * N_NODES + jB];
        const int adj1A = adj[i1 * N_NODES + jA];
        const int adj1B = adj[i1 * N_NODES + jB];

        // build A fragments for both i's (pure bf16x2 SIMD: 3 instr/pack)
        uint32_t af0[4][4], af1[4][4];
        #pragma unroll
        for (int s = 0; s < 4; ++s) {
            const int kp = 8 * s + tig;
            const uint32_t e0a = sEiH[ii0][kp];
            const uint32_t e0b = sEiH[ii0][kp + 4];
            const uint32_t e1a = sEiH[ii1][kp];
            const uint32_t e1b = sEiH[ii1][kp + 4];
            af0[s][0] = leakyadd2(e0a, ejaH0[s]);
            af0[s][1] = leakyadd2(e0a, ejaH1[s]);
            af0[s][2] = leakyadd2(e0b, ejbH0[s]);
            af0[s][3] = leakyadd2(e0b, ejbH1[s]);
            af1[s][0] = leakyadd2(e1a, ejaH0[s]);
            af1[s][1] = leakyadd2(e1a, ejaH1[s]);
            af1[s][2] = leakyadd2(e1b, ejbH0[s]);
            af1[s][3] = leakyadd2(e1b, ejbH1[s]);
        }

        // acc init = qi + kj(regs) for both i's
        float acc0[8][4], acc1[8][4];
        #pragma unroll
        for (int nt = 0; nt < 8; ++nt) {
            const int off = 8 * nt + 2 * tig;
            const float2 q0 = *(const float2*)&sQi[ii0][off];
            const float2 q1 = *(const float2*)&sQi[ii1][off];
            acc0[nt][0] = q0.x + kj0r[nt].x; acc0[nt][1] = q0.y + kj0r[nt].y;
            acc0[nt][2] = q0.x + kj1r[nt].x; acc0[nt][3] = q0.y + kj1r[nt].y;
            acc1[nt][0] = q1.x + kj0r[nt].x; acc1[nt][1] = q1.y + kj0r[nt].y;
            acc1[nt][2] = q1.x + kj1r[nt].x; acc1[nt][3] = q1.y + kj1r[nt].y;
        }

        // interleaved MMA sets: 16 independent chains (tensor pipe ONLY here)
        #pragma unroll
        for (int s = 0; s < 4; ++s) {
            #pragma unroll
            for (int nt = 0; nt < 8; ++nt) {
                mma_bf16_16x8x16(acc0[nt][0], acc0[nt][1], acc0[nt][2], acc0[nt][3],
                                 af0[s][0], af0[s][1], af0[s][2], af0[s][3],
                                 Bf[s][nt][0], Bf[s][nt][1]);
                mma_bf16_16x8x16(acc1[nt][0], acc1[nt][1], acc1[nt][2], acc1[nt][3],
                                 af1[s][0], af1[s][1], af1[s][2], af1[s][3],
                                 Bf[s][nt][0], Bf[s][nt][1]);
            }
        }

        // ---- SCALAR epilogue (fma pipe): leaky + dot w2, quad-reduce ----
        float e00 = 0.f, e01 = 0.f, e10 = 0.f, e11 = 0.f;
        #pragma unroll
        for (int nt = 0; nt < 8; ++nt) {
            const int off = 8 * nt + 2 * tig;
            const float w0 = sW2[off];
            const float w1 = sW2[off + 1];
            e00 = fmaf(leaky(acc0[nt][0]), w0, e00);
            e10 = fmaf(leaky(acc1[nt][0]), w0, e10);
            e00 = fmaf(leaky(acc0[nt][1]), w1, e00);
            e10 = fmaf(leaky(acc1[nt][1]), w1, e10);
            e01 = fmaf(leaky(acc0[nt][2]), w0, e01);
            e11 = fmaf(leaky(acc1[nt][2]), w0, e11);
            e01 = fmaf(leaky(acc0[nt][3]), w1, e01);
            e11 = fmaf(leaky(acc1[nt][3]), w1, e11);
        }
        e00 += __shfl_xor_sync(0xffffffffu, e00, 1);
        e10 += __shfl_xor_sync(0xffffffffu, e10, 1);
        e01 += __shfl_xor_sync(0xffffffffu, e01, 1);
        e11 += __shfl_xor_sync(0xffffffffu, e11, 1);
        e00 += __shfl_xor_sync(0xffffffffu, e00, 2);
        e10 += __shfl_xor_sync(0xffffffffu, e10, 2);
        e01 += __shfl_xor_sync(0xffffffffu, e01, 2);
        e11 += __shfl_xor_sync(0xffffffffu, e11, 2);
        if (tig == 0) {
            float a0 = e00 + b2, a1 = e01 + b2;
            float d0 = e10 + b2, d1 = e11 + b2;
            if (adj0A == 0) a0 = MASK_VAL_F;
            if (adj0B == 0) a1 = MASK_VAL_F;
            if (adj1A == 0) d0 = MASK_VAL_F;
            if (adj1B == 0) d1 = MASK_VAL_F;
            g_e[i0 * N_NODES + jA] = a0;
            g_e[i0 * N_NODES + jB] = a1;
            g_e[i1 * N_NODES + jA] = d0;
            g_e[i1 * N_NODES + jB] = d1;
        }
    }
}

// ================================================================
// Kernel 3: softmax + aggregate + LN; 8 rows per block (Wh reuse, 1 wave).
// No max pass — e analytically bounded; masked -1e9 underflows via -87 clamp.
// ================================================================
#define R8 8
__global__ void __launch_bounds__(256) softmax_ln_kernel(
    const float* __restrict__ h, const float* __restrict__ ln_g,
    const float* __restrict__ ln_b, float* __restrict__ out)
{
    __shared__ float sp[R8][N_NODES];       // 32KB
    __shared__ float red[R8][8];
    __shared__ float part[R8][4][64];       // 8KB
    __shared__ float shp[R8][64];
    __shared__ float sInv[R8], sMu[R8], sVar[R8];

    const int i0 = blockIdx.x * R8;
    const int t = threadIdx.x;
    const int lane = t & 31, wid = t >> 5;

    float s[R8];
    #pragma unroll
    for (int r = 0; r < R8; ++r) s[r] = 0.f;
    for (int j = t; j < N_NODES; j += 256) {
        #pragma unroll
        for (int r = 0; r < R8; ++r) {
            const float v = g_e[(i0 + r) * N_NODES + j];
            const float p = __expf(fmaxf(v, -87.0f));
            sp[r][j] = p;
            s[r] += p;
        }
    }
    #pragma unroll
    for (int r = 0; r < R8; ++r) {
        s[r] = warpReduceSum(s[r]);
        if (lane == 0) red[r][wid] = s[r];
    }
    __syncthreads();
    if (t < R8) {
        float ss = 0.f;
        #pragma unroll
        for (int w = 0; w < 8; ++w) ss += red[t][w];
        sInv[t] = 1.0f / ss;
    }
    __syncthreads();

    const int g = t >> 6, d = t & 63;
    const int jb = g * 256;
    float a[R8];
    #pragma unroll
    for (int r = 0; r < R8; ++r) a[r] = 0.f;
    #pragma unroll 2
    for (int jj = 0; jj < 256; jj += 4) {
        const float w0 = g_Wh[(jb + jj + 0) * D + d];
        const float w1 = g_Wh[(jb + jj + 1) * D + d];
        const float w2 = g_Wh[(jb + jj + 2) * D + d];
        const float w3 = g_Wh[(jb + jj + 3) * D + d];
        #pragma unroll
        for (int r = 0; r < R8; ++r) {
            const float4 p = *(const float4*)&sp[r][jb + jj];
            a[r] += p.x * w0 + p.y * w1 + p.z * w2 + p.w * w3;
        }
    }
    #pragma unroll
    for (int r = 0; r < R8; ++r) part[r][g][d] = a[r];
    __syncthreads();

    #pragma unroll
    for (int it = 0; it < 2; ++it) {
        const int idx = t + it * 256;
        const int r = idx >> 6, dd = idx & 63;
        const float hp = (part[r][0][dd] + part[r][1][dd] + part[r][2][dd] + part[r][3][dd])
                         * sInv[r] + h[(i0 + r) * D + dd];
        shp[r][dd] = hp;
    }
    __syncthreads();

    {
        const int r = wid;
        float v = shp[r][lane] + shp[r][lane + 32];
        v = warpReduceSum(v);
        if (lane == 0) sMu[r] = v * (1.0f / 64.0f);
    }
    __syncthreads();
    {
        const int r = wid;
        const float mu = sMu[r];
        const float d0 = shp[r][lane] - mu, d1 = shp[r][lane + 32] - mu;
        float v = d0 * d0 + d1 * d1;
        v = warpReduceSum(v);
        if (lane == 0) sVar[r] = v * (1.0f / 64.0f);
    }
    __syncthreads();

    #pragma unroll
    for (int it = 0; it < 2; ++it) {
        const int idx = t + it * 256;
        const int r = idx >> 6, dd = idx & 63;
        const float mu = sMu[r];
        const float rstd = rsqrtf(sVar[r] + LN_EPS_F);
        out[(i0 + r) * D + dd] = (shp[r][dd] - mu) * rstd * ln_g[dd] + ln_b[dd];
    }
}

// ================================================================
extern "C" void kernel_launch(void* const* d_in, const int* in_sizes, int n_in,
                              void* d_out, int out_size) {
    const float* h        = (const float*)d_in[0];
    const int*   adj      = (const int*)  d_in[1];
    const float* W        = (const float*)d_in[2];
    const float* attn_w1  = (const float*)d_in[3];
    const float* attn_b1  = (const float*)d_in[4];
    const float* attn_w2  = (const float*)d_in[5];
    const float* attn_b2  = (const float*)d_in[6];
    const float* edge_w   = (const float*)d_in[7];
    const float* edge_b   = (const float*)d_in[8];
    const float* ln_g     = (const float*)d_in[9];
    const float* ln_b     = (const float*)d_in[10];
    float* out = (float*)d_out;

    prep_kernel<<<N_NODES / 8, 256>>>(h, W, attn_w1, attn_b1, edge_w, edge_b);

    dim3 grid(N_NODES / 128, N_ICHUNKS);
    escore_hmma_kernel<<<grid, 256>>>(attn_w1, attn_w2, attn_b2, adj);

    softmax_ln_kernel<<<N_NODES / R8, 256>>>(h, ln_g, ln_b, out);
}